// round 9
// baseline (speedup 1.0000x reference)
#include <cuda_runtime.h>
#include <cuda_fp16.h>
#include <cstdint>

// Problem constants
#define B_      32
#define NTOK    3136
#define DIMC    768
#define DIM3    2304
#define HEADS   12
#define HD      64
#define NW      49
#define WS      16
#define TPW     64
#define MTOK    784
#define KDIM    768

#define NELEM_X   ((size_t)B_ * NTOK * DIMC)
#define NELEM_O   ((size_t)B_ * MTOK * DIMC)
#define WQT_ELEMS ((size_t)DIM3 * DIMC)
#define WPT_ELEMS ((size_t)DIMC * DIMC)

// Scratch (device globals: allocation-free rule)
__device__ __half g_qkv[(size_t)B_ * NTOK * DIM3];   // fp16 qkv
__device__ __half g_xh[NELEM_X];
__device__ __half g_oh[NELEM_O];
__device__ __half g_wt[WQT_ELEMS + WPT_ELEMS];       // [N][K] transposed, fp16

// ---------------------------------------------------------------------------
// PTX helpers
// ---------------------------------------------------------------------------
__device__ __forceinline__ uint32_t smem_u32(const void* p) {
    uint32_t a;
    asm("{ .reg .u64 t; cvta.to.shared.u64 t, %1; cvt.u32.u64 %0, t; }" : "=r"(a) : "l"(p));
    return a;
}
#define CP_ASYNC16(dst, src) \
    asm volatile("cp.async.cg.shared.global [%0], [%1], 16;" :: "r"(dst), "l"(src))
#define CP_COMMIT() asm volatile("cp.async.commit_group;" ::: "memory")
#define CP_WAIT1()  asm volatile("cp.async.wait_group 1;" ::: "memory")

#define LDSM4(r, addr) \
    asm volatile("ldmatrix.sync.aligned.m8n8.x4.shared.b16 {%0,%1,%2,%3}, [%4];" \
                 : "=r"((r)[0]), "=r"((r)[1]), "=r"((r)[2]), "=r"((r)[3]) : "r"(addr))

#define MMA_F16(c, a, b0, b1) \
    asm volatile("mma.sync.aligned.m16n8k16.row.col.f32.f16.f16.f32 " \
                 "{%0,%1,%2,%3}, {%4,%5,%6,%7}, {%8,%9}, {%0,%1,%2,%3};" \
                 : "+f"((c)[0]), "+f"((c)[1]), "+f"((c)[2]), "+f"((c)[3]) \
                 : "r"((a)[0]), "r"((a)[1]), "r"((a)[2]), "r"((a)[3]), \
                   "r"(b0), "r"(b1))

// ---------------------------------------------------------------------------
// fp16 GEMM: C[M,N] = A[M,K] @ W[K,N] + bias, W transposed [N][K].
// Tile 256(M) x 128(N), 8 warps, warp grid 4(M) x 2(N), warp tile 64x64.
// KC=64. SMEM row = 64 fp16 = 128B, chunk g at (g ^ (r&7))*16 (conflict-free).
// 3-stage cp.async ring, one barrier/stage, 1 CTA/SM.
// Per k16 step: 8 LDSM.x4 feed 32 MMAs -> 128 B/MMA crossbar traffic.
// ---------------------------------------------------------------------------
#define TILE_M    256
#define TILE_N    128
#define KC        64
#define A_BYTES   32768                 // 256 rows * 128B
#define B_OFF     32768
#define STG_BYTES 49152                 // A + B (128 rows * 128B)
#define NSTAGE    3
#define GEMM_SMEM (NSTAGE * STG_BYTES)  // 147456

__device__ __forceinline__ void load_stage(
    const __half* __restrict__ A, const __half* __restrict__ Bt,
    int m0, int n0, int kt, int K, uint32_t buf, int tid)
{
    #pragma unroll
    for (int i = 0; i < 12; ++i) {
        int idx = tid + i * 256;          // 0..3071
        int mat = idx >> 11;              // 0 = A (2048 chunks), 1 = B (1024)
        int c   = idx & 2047;
        int r   = c >> 3;                 // A: 0..255 / B: 0..127
        int g   = c & 7;                  // 16B chunk (8 fp16)
        const __half* src = (mat ? Bt : A)
                          + (size_t)((mat ? n0 : m0) + r) * K + kt + g * 8;
        uint32_t dst = buf + mat * B_OFF + r * 128 + ((g ^ (r & 7)) * 16);
        CP_ASYNC16(dst, src);
    }
    CP_COMMIT();
}

template <int OUT_HALF>
__global__ __launch_bounds__(256, 1)
void gemm_f16_kernel(const __half* __restrict__ A, const __half* __restrict__ Bt,
                     const float* __restrict__ bias, void* __restrict__ Cv,
                     int M, int N, int K)
{
    extern __shared__ char smem[];
    const uint32_t sb = smem_u32(smem);
    const int tid = threadIdx.x, wid = tid >> 5, lane = tid & 31;
    const int wm = wid & 3, wn = wid >> 2;        // warp grid 4(M) x 2(N)
    const int m0 = blockIdx.y * TILE_M;
    const int n0 = blockIdx.x * TILE_N;

    float acc[4][8][4];                   // [mt][nt][frag]
    #pragma unroll
    for (int mt = 0; mt < 4; ++mt)
        #pragma unroll
        for (int nt = 0; nt < 8; ++nt)
            #pragma unroll
            for (int j = 0; j < 4; ++j) acc[mt][nt][j] = 0.f;

    const int NST = K / KC;               // 12
    load_stage(A, Bt, m0, n0, 0,  K, sb,             tid);
    load_stage(A, Bt, m0, n0, KC, K, sb + STG_BYTES, tid);

    // per-lane ldmatrix geometry
    const int a_row  = wm * 64 + (lane & 15);             // + mt*16
    const int a_csel = lane >> 4;                         // 0/1 (k-half)
    const int a_sx   = a_row & 7;                         // invariant under +16
    const uint32_t a_base = (uint32_t)a_row * 128;
    const int b_row  = wn * 64 + (lane & 7) + ((lane & 16) ? 8 : 0);  // + p*16
    const int b_csel = (lane >> 3) & 1;
    const int b_sx   = b_row & 7;
    const uint32_t b_base = B_OFF + (uint32_t)b_row * 128;

    for (int s = 0; s < NST; ++s) {
        const uint32_t buf = sb + (uint32_t)(s % NSTAGE) * STG_BYTES;
        CP_WAIT1();
        __syncthreads();
        if (s + 2 < NST)
            load_stage(A, Bt, m0, n0, (s + 2) * KC, K,
                       sb + (uint32_t)((s + 2) % NSTAGE) * STG_BYTES, tid);
        else
            CP_COMMIT();                  // empty group keeps wait counts aligned

        #pragma unroll
        for (int j = 0; j < 4; ++j) {     // four k16 steps per stage
            uint32_t af[4][4], bf[4][4];
            const uint32_t a_co = ((2 * j + a_csel) ^ a_sx) * 16;
            const uint32_t b_co = ((2 * j + b_csel) ^ b_sx) * 16;
            #pragma unroll
            for (int mt = 0; mt < 4; ++mt)
                LDSM4(af[mt], buf + a_base + mt * (16 * 128) + a_co);
            #pragma unroll
            for (int p = 0; p < 4; ++p)
                LDSM4(bf[p], buf + b_base + p * (16 * 128) + b_co);
            // 32 MMAs; consecutive MMAs never share an accumulator
            #pragma unroll
            for (int p = 0; p < 4; ++p)
                #pragma unroll
                for (int mt = 0; mt < 4; ++mt) {
                    MMA_F16(acc[mt][2 * p],     af[mt], bf[p][0], bf[p][1]);
                    MMA_F16(acc[mt][2 * p + 1], af[mt], bf[p][2], bf[p][3]);
                }
        }
        // no trailing sync: next stage's barrier fences buffer reuse
    }

    // Epilogue: registers -> gmem with bias
    #pragma unroll
    for (int nt = 0; nt < 8; ++nt) {
        const int col = n0 + wn * 64 + nt * 8 + (lane & 3) * 2;
        const float2 bi = *(const float2*)&bias[col];
        #pragma unroll
        for (int mt = 0; mt < 4; ++mt) {
            const int row = m0 + wm * 64 + mt * 16 + (lane >> 2);
            if (OUT_HALF) {
                __half* C = (__half*)Cv;
                __half2 v0 = __floats2half2_rn(acc[mt][nt][0] + bi.x,
                                               acc[mt][nt][1] + bi.y);
                __half2 v1 = __floats2half2_rn(acc[mt][nt][2] + bi.x,
                                               acc[mt][nt][3] + bi.y);
                *(__half2*)&C[(size_t)row * N + col]       = v0;
                *(__half2*)&C[(size_t)(row + 8) * N + col] = v1;
            } else {
                float* C = (float*)Cv;
                float2 v0 = make_float2(acc[mt][nt][0] + bi.x, acc[mt][nt][1] + bi.y);
                float2 v1 = make_float2(acc[mt][nt][2] + bi.x, acc[mt][nt][3] + bi.y);
                *(float2*)&C[(size_t)row * N + col]       = v0;
                *(float2*)&C[(size_t)(row + 8) * N + col] = v1;
            }
        }
    }
}

// ---------------------------------------------------------------------------
// x -> fp16
// ---------------------------------------------------------------------------
__global__ void xconv_kernel(const float* __restrict__ X, __half* __restrict__ H, int n4)
{
    int i = blockIdx.x * blockDim.x + threadIdx.x;
    if (i >= n4) return;
    float4 v = ((const float4*)X)[i];
    ((__half2*)H)[2 * i]     = __floats2half2_rn(v.x, v.y);
    ((__half2*)H)[2 * i + 1] = __floats2half2_rn(v.z, v.w);
}

// ---------------------------------------------------------------------------
// W[K][N] -> W^T fp16 [N][K]
// ---------------------------------------------------------------------------
__global__ void wconv_kernel(const float* __restrict__ W, __half* __restrict__ Wt,
                             int K, int N)
{
    __shared__ float t[32][33];
    const int nb = blockIdx.x * 32, kb = blockIdx.y * 32;
    const int tx = threadIdx.x, ty = threadIdx.y;   // block (32, 8)
    #pragma unroll
    for (int j = 0; j < 4; ++j)
        t[ty + 8 * j][tx] = W[(size_t)(kb + ty + 8 * j) * N + nb + tx];
    __syncthreads();
    #pragma unroll
    for (int j = 0; j < 4; ++j) {
        int n = nb + ty + 8 * j, k = kb + tx;
        Wt[(size_t)n * K + k] = __float2half_rn(t[tx][ty + 8 * j]);
    }
}

// ---------------------------------------------------------------------------
// Windowed attention. qkv fp16 (half2 loads), math fp32, output fp16.
// ---------------------------------------------------------------------------
__global__ __launch_bounds__(128)
void attn_kernel(const __half* __restrict__ qkv, __half* __restrict__ oh)
{
    const int w = blockIdx.x, h = blockIdx.y, b = blockIdx.z;
    __shared__ float ks[TPW][HD + 1];
    __shared__ float vs[TPW][HD + 1];
    __shared__ float qp[WS][HD + 1];
    __shared__ float at[WS][TPW + 1];

    const int tid = threadIdx.x;
    const size_t base = (size_t)b * NTOK * DIM3;
    const int hoff = h * HD;

    #pragma unroll
    for (int i = 0; i < 16; ++i) {
        int idx = tid + i * 128;          // 0..2047 half2 slots
        int t = idx >> 5, d2 = idx & 31;
        size_t off = base + (size_t)(t * NW + w) * DIM3 + hoff + 2 * d2;
        float2 kv = __half22float2(*(const __half2*)&qkv[off + DIMC]);
        float2 vv = __half22float2(*(const __half2*)&qkv[off + 2 * DIMC]);
        ks[t][2 * d2] = kv.x; ks[t][2 * d2 + 1] = kv.y;
        vs[t][2 * d2] = vv.x; vs[t][2 * d2 + 1] = vv.y;
    }
    #pragma unroll
    for (int i = 0; i < 4; ++i) {
        int idx = tid + i * 128;          // 0..511 half2 slots
        int qi = idx >> 5, d2 = idx & 31;
        float2 m = make_float2(-3.0e38f, -3.0e38f);
        #pragma unroll
        for (int s = 0; s < 4; ++s) {
            int t = s * WS + qi;
            float2 v = __half22float2(*(const __half2*)
                &qkv[base + (size_t)(t * NW + w) * DIM3 + hoff + 2 * d2]);
            m.x = fmaxf(m.x, v.x); m.y = fmaxf(m.y, v.y);
        }
        qp[qi][2 * d2] = m.x; qp[qi][2 * d2 + 1] = m.y;
    }
    __syncthreads();

    const float scale = 0.125f;
    #pragma unroll
    for (int i = 0; i < 8; ++i) {
        int idx = tid + i * 128;
        int qi = idx >> 6, t = idx & 63;
        float s = 0.f;
        #pragma unroll
        for (int d = 0; d < HD; ++d)
            s = fmaf(qp[qi][d], ks[t][d], s);
        at[qi][t] = s * scale;
    }
    __syncthreads();

    const int lane = tid & 31, wj = tid >> 5;
    for (int r = wj * 4; r < wj * 4 + 4; ++r) {
        float x0 = at[r][lane], x1 = at[r][lane + 32];
        float m = fmaxf(x0, x1);
        #pragma unroll
        for (int o = 16; o; o >>= 1)
            m = fmaxf(m, __shfl_xor_sync(0xffffffffu, m, o));
        float e0 = __expf(x0 - m), e1 = __expf(x1 - m);
        float s = e0 + e1;
        #pragma unroll
        for (int o = 16; o; o >>= 1)
            s += __shfl_xor_sync(0xffffffffu, s, o);
        float inv = 1.f / s;
        at[r][lane]      = e0 * inv;
        at[r][lane + 32] = e1 * inv;
    }
    __syncthreads();

    #pragma unroll
    for (int i = 0; i < 8; ++i) {
        int idx = tid + i * 128;
        int qi = idx >> 6, d = idx & 63;
        float s = 0.f;
        #pragma unroll
        for (int t = 0; t < TPW; ++t)
            s = fmaf(at[qi][t], vs[t][d], s);
        int m = qi * NW + w;
        oh[((size_t)b * MTOK + m) * DIMC + hoff + d] = __float2half_rn(s);
    }
}

// ---------------------------------------------------------------------------
extern "C" void kernel_launch(void* const* d_in, const int* in_sizes, int n_in,
                              void* d_out, int out_size)
{
    const float* x     = (const float*)d_in[0];
    const float* Wqkv  = (const float*)d_in[1];
    const float* bqkv  = (const float*)d_in[2];
    const float* Wproj = (const float*)d_in[3];
    const float* bproj = (const float*)d_in[4];
    float* out = (float*)d_out;

    __half *qkvp, *xh, *oh, *wt;
    cudaGetSymbolAddress((void**)&qkvp, g_qkv);
    cudaGetSymbolAddress((void**)&xh, g_xh);
    cudaGetSymbolAddress((void**)&oh, g_oh);
    cudaGetSymbolAddress((void**)&wt, g_wt);

    cudaFuncSetAttribute(gemm_f16_kernel<0>,
                         cudaFuncAttributeMaxDynamicSharedMemorySize, GEMM_SMEM);
    cudaFuncSetAttribute(gemm_f16_kernel<1>,
                         cudaFuncAttributeMaxDynamicSharedMemorySize, GEMM_SMEM);

    // 0a) x -> fp16
    {
        int n4 = (int)(NELEM_X / 4);
        xconv_kernel<<<n4 / 256, 256>>>(x, xh, n4);
    }
    // 0b) transpose weights -> fp16 [N][K]
    {
        dim3 b(32, 8);
        wconv_kernel<<<dim3(DIM3 / 32, DIMC / 32), b>>>(Wqkv, wt, DIMC, DIM3);
        wconv_kernel<<<dim3(DIMC / 32, DIMC / 32), b>>>(Wproj, wt + WQT_ELEMS,
                                                        DIMC, DIMC);
    }
    // 1) QKV projection -> fp16 qkv
    {
        dim3 grid(DIM3 / TILE_N, (B_ * NTOK) / TILE_M);   // (18, 392)
        gemm_f16_kernel<1><<<grid, 256, GEMM_SMEM>>>(xh, wt, bqkv, qkvp,
                                                     B_ * NTOK, DIM3, KDIM);
    }
    // 2) windowed attention with query max-pool
    {
        dim3 grid(NW, HEADS, B_);
        attn_kernel<<<grid, 128>>>(qkvp, oh);
    }
    // 3) output projection -> fp32 out
    {
        dim3 grid(DIMC / TILE_N, (B_ * MTOK) / TILE_M);   // (6, 98)
        gemm_f16_kernel<0><<<grid, 256, GEMM_SMEM>>>(oh, wt + WQT_ELEMS,
                                                     bproj, out, B_ * MTOK, DIMC, KDIM);
    }
}